// round 6
// baseline (speedup 1.0000x reference)
#include <cuda_runtime.h>

#define HW   16384      // 128*128
#define NCH  256
#define NB   8
#define PAIRS 65536     // 131072 pixels / 2
#define NPIX 131072

typedef unsigned long long u64;

// ---------------- packed f32x2 helpers (sm_103a) ----------------
__device__ __forceinline__ u64 fma2(u64 a, u64 b, u64 c) {
    u64 d; asm("fma.rn.f32x2 %0,%1,%2,%3;" : "=l"(d) : "l"(a), "l"(b), "l"(c)); return d;
}
__device__ __forceinline__ u64 pk2(float x, float y) {
    u64 r; asm("mov.b64 %0,{%1,%2};" : "=l"(r) : "f"(x), "f"(y)); return r;
}
__device__ __forceinline__ float sig1(float x) {
    return __fdividef(1.f, 1.f + __expf(-x));
}

// 22 partial dot products per pixel-pair, [o][pairIdx] layout (u64 = 2 px)
__device__ u64 g_scratch[22 * PAIRS];

// Output offsets (tuple flattened: xh_u_new, xh_l_new, att_u, att_l)
#define OUT_XHL  1310720
#define OUT_ATTU 2621440
#define OUT_ATTL 2752512

// =========================================================================
// Kernel 1: [px x 256] @ [256 x 22] streaming GEMM over h_fea.
// Output-split: 2 threads per pixel-pair, 11 outputs each.
// Register double-buffer software pipeline, sustained MLP = 8.
// smem weights: [c][half][12] u64 (padded to 12 -> 6 aligned LDS.128/half)
// =========================================================================
__global__ __launch_bounds__(128, 4) void k1_main(
    const float* __restrict__ h_fea,
    const float* __restrict__ pdp_w1,
    const float* __restrict__ dU_aw,
    const float* __restrict__ dL_aw)
{
    __shared__ u64 swk[256 * 24];           // 49152 B
    const int tid = threadIdx.x;

    for (int idx = tid; idx < 256 * 24; idx += 128) {
        int c = idx / 24, r = idx - c * 24;
        int h = r / 12, k = r - h * 12;
        int o = h * 11 + k;
        float v = 0.f;
        if (k < 11)
            v = (o < 20) ? pdp_w1[o * 276 + c] : ((o == 20) ? dU_aw[c] : dL_aw[c]);
        swk[idx] = pk2(v, v);
    }
    __syncthreads();

    const int t    = blockIdx.x * 128 + tid;    // 131072 threads total
    const int pair = t >> 1;
    const int hoff = (t & 1) * 12;              // which 11-output half
    const int P  = pair * 2;
    const int n  = P >> 14;
    const int pp = P & (HW - 1);
    const float* hb = h_fea + n * (NCH * HW) + pp;

    u64 acc[11];
#pragma unroll
    for (int o = 0; o < 11; o++) acc[o] = 0ull;

    u64 bA[8], bB[8];

#define LOAD_CHUNK(B, C0)                                                     \
    _Pragma("unroll")                                                         \
    for (int j = 0; j < 8; j++)                                               \
        B[j] = *reinterpret_cast<const u64*>(hb + ((C0) + j) * HW);

#define COMP_CHUNK(B, C0)                                                     \
    _Pragma("unroll")                                                         \
    for (int j = 0; j < 8; j++) {                                             \
        u64 xx = B[j];                                                        \
        const ulonglong2* w = reinterpret_cast<const ulonglong2*>(            \
            &swk[((C0) + j) * 24 + hoff]);                                    \
        _Pragma("unroll")                                                     \
        for (int o = 0; o < 5; o++) {                                         \
            ulonglong2 wv = w[o];                                             \
            acc[2 * o]     = fma2(xx, wv.x, acc[2 * o]);                      \
            acc[2 * o + 1] = fma2(xx, wv.y, acc[2 * o + 1]);                  \
        }                                                                     \
        { ulonglong2 wv = w[5];                                               \
          acc[10] = fma2(xx, wv.x, acc[10]); }                                \
    }

    LOAD_CHUNK(bA, 0)
#pragma unroll 1
    for (int c0 = 0; c0 < 256; c0 += 16) {
        LOAD_CHUNK(bB, c0 + 8)
        COMP_CHUNK(bA, c0)
        const int nxt = (c0 + 16) & 255;      // last iter reloads chunk 0 (dead)
        LOAD_CHUNK(bA, nxt)
        COMP_CHUNK(bB, c0 + 8)
    }
#undef LOAD_CHUNK
#undef COMP_CHUNK

    const int obase = (hoff == 12) ? 11 : 0;
#pragma unroll
    for (int o = 0; o < 11; o++)
        g_scratch[(obase + o) * PAIRS + pair] = acc[o];
}

// =========================================================================
// Kernel 2: tails + graph logic — SCALAR, 1 pixel/thread. (unchanged)
// =========================================================================
#define SB 440
#define O_W2    0
#define O_ATTW  200
#define O_ATTB  220
#define O_CUAW  222
#define O_CUAB  262
#define O_CUW   266
#define O_CLAW  466
#define O_CLAB  486
#define O_CLW   488
#define O_DUB   688
#define O_DUW   689
#define O_DLB   789
#define O_DLW   790
#define O_GUW   890
#define O_GUB   1090
#define O_CDUW  1100
#define O_GLW   1300
#define O_GLB   1500
#define O_CDLW  1510
#define SM2_F32 (SB + 1710)

__global__ __launch_bounds__(128, 4) void k2_post(
    const float* __restrict__ xh_u, const float* __restrict__ xh_l,
    const float* __restrict__ xf, const float* __restrict__ xp,
    const float* __restrict__ pdp_w1, const float* __restrict__ pdp_w2,
    const float* __restrict__ att_w, const float* __restrict__ att_b,
    const float* __restrict__ cU_aw, const float* __restrict__ cU_ab, const float* __restrict__ cU_w,
    const float* __restrict__ cL_aw, const float* __restrict__ cL_ab, const float* __restrict__ cL_w,
    const float* __restrict__ dU_aw, const float* __restrict__ dU_ab, const float* __restrict__ dU_w,
    const float* __restrict__ dL_aw, const float* __restrict__ dL_ab, const float* __restrict__ dL_w,
    const float* __restrict__ gU_w, const float* __restrict__ gU_b, const float* __restrict__ cdU_w,
    const float* __restrict__ gL_w, const float* __restrict__ gL_b, const float* __restrict__ cdL_w,
    float* __restrict__ out)
{
    __shared__ float sw[SM2_F32];           // 8.6 KB
    const int tid = threadIdx.x;

    for (int idx = tid; idx < 400; idx += 128) {
        int o = idx / 20, i = idx - o * 20;
        sw[idx] = pdp_w1[o * 276 + 256 + i];      // cat [h_fea, xh_u, xh_l]
    }
    if (tid < 20) {
        sw[400 + tid] = dU_aw[256 + tid];         // [h_fea, xf, xh_u]
        sw[420 + tid] = dL_aw[256 + tid];         // [h_fea, xf, xh_l]
    }
#define CPY(src, n_, off) for (int j = tid; j < (n_); j += 128) sw[SB + (off) + j] = (src)[j];
    CPY(pdp_w2, 200, O_W2)
    CPY(att_w, 20, O_ATTW)
    CPY(att_b, 2, O_ATTB)
    CPY(cU_aw, 40, O_CUAW)
    CPY(cU_ab, 4, O_CUAB)
    CPY(cU_w, 200, O_CUW)
    CPY(cL_aw, 20, O_CLAW)
    CPY(cL_ab, 2, O_CLAB)
    CPY(cL_w, 200, O_CLW)
    CPY(dU_ab, 1, O_DUB)
    CPY(dU_w, 100, O_DUW)
    CPY(dL_ab, 1, O_DLB)
    CPY(dL_w, 100, O_DLW)
    CPY(gU_w, 200, O_GUW)
    CPY(gU_b, 10, O_GUB)
    CPY(cdU_w, 200, O_CDUW)
    CPY(gL_w, 200, O_GLW)
    CPY(gL_b, 10, O_GLB)
    CPY(cdL_w, 200, O_CDLW)
#undef CPY
    __syncthreads();

    const int P  = blockIdx.x * 128 + tid;  // one pixel per thread
    const int n  = P >> 14;
    const int pp = P & (HW - 1);

    const float* gsf = reinterpret_cast<const float*>(g_scratch);

    float acc[22];
#pragma unroll
    for (int o = 0; o < 22; o++) acc[o] = gsf[o * NPIX + P];

    const int base10 = n * 10 * HW + pp;
    float xu[10], xl[10], xfv[10];
#pragma unroll
    for (int i = 0; i < 10; i++) {
        xu[i]  = xh_u[base10 + i * HW];
        xl[i]  = xh_l[base10 + i * HW];
        xfv[i] = xf[base10 + i * HW];
    }

    // tails of the 276-channel dot products
#pragma unroll
    for (int o = 0; o < 20; o++) {
        float a = acc[o];
#pragma unroll
        for (int i = 0; i < 10; i++) {
            a = fmaf(xu[i], sw[o * 20 + i], a);
            a = fmaf(xl[i], sw[o * 20 + 10 + i], a);
        }
        acc[o] = a;
    }
    {
        float a = acc[20];
#pragma unroll
        for (int i = 0; i < 10; i++) {
            a = fmaf(xfv[i], sw[400 + i], a);
            a = fmaf(xu[i],  sw[410 + i], a);
        }
        acc[20] = a;
        float b = acc[21];
#pragma unroll
        for (int i = 0; i < 10; i++) {
            b = fmaf(xfv[i], sw[420 + i], b);
            b = fmaf(xl[i],  sw[430 + i], b);
        }
        acc[21] = b;
    }

    const float attu = sig1(acc[20] + sw[SB + O_DUB]);
    const float attl = sig1(acc[21] + sw[SB + O_DLB]);

#pragma unroll
    for (int o = 0; o < 20; o++) acc[o] = fmaxf(acc[o], 0.f);

    // dp grouped 10x10
    float dpu[10], dpl[10];
#pragma unroll
    for (int j = 0; j < 10; j++) {
        float s = 0.f, s2 = 0.f;
#pragma unroll
        for (int i = 0; i < 10; i++) {
            s  = fmaf(acc[i],      sw[SB + O_W2 + j * 10 + i], s);
            s2 = fmaf(acc[10 + i], sw[SB + O_W2 + 100 + j * 10 + i], s2);
        }
        dpu[j] = fmaxf(s, 0.f);
        dpl[j] = fmaxf(s2, 0.f);
    }

    // grouped gate attention
    float au = sw[SB + O_ATTB + 0], al = sw[SB + O_ATTB + 1];
#pragma unroll
    for (int i = 0; i < 10; i++) {
        au = fmaf(xu[i], sw[SB + O_ATTW + i], au);
        al = fmaf(xl[i], sw[SB + O_ATTW + 10 + i], al);
    }
    au = sig1(au);
    al = sig1(al);

    float m[10];

    // =================== U branch ===================
    {
        float msg0 = 0.f, msg1 = 0.f, msg2 = 0.f, msg3 = 0.f, msg4 = 0.f,
              msg5 = 0.f, msg6 = 0.f, msg7 = 0.f, msg8 = 0.f, msg9 = 0.f;
#pragma unroll
        for (int p = 0; p < 4; p++) {
            float ca = sw[SB + O_CUAB + p];
            float pv[10];
#pragma unroll
            for (int i = 0; i < 10; i++) {
                pv[i] = xp[((p * NB + n) * 10 + i) * HW + pp];
                ca = fmaf(pv[i], sw[SB + O_CUAW + p * 10 + i], ca);
            }
            ca = sig1(ca);
            msg0 = fmaf(pv[0], ca, msg0); msg1 = fmaf(pv[1], ca, msg1);
            msg2 = fmaf(pv[2], ca, msg2); msg3 = fmaf(pv[3], ca, msg3);
            msg4 = fmaf(pv[4], ca, msg4); msg5 = fmaf(pv[5], ca, msg5);
            msg6 = fmaf(pv[6], ca, msg6); msg7 = fmaf(pv[7], ca, msg7);
            msg8 = fmaf(pv[8], ca, msg8); msg9 = fmaf(pv[9], ca, msg9);
        }
        float msg[10] = {msg0, msg1, msg2, msg3, msg4, msg5, msg6, msg7, msg8, msg9};
#pragma unroll
        for (int j = 0; j < 10; j++) {
            float s = 0.f;
#pragma unroll
            for (int i = 0; i < 10; i++) s = fmaf(xu[i],  sw[SB + O_CUW + j * 20 + i], s);
#pragma unroll
            for (int i = 0; i < 10; i++) s = fmaf(msg[i], sw[SB + O_CUW + j * 20 + 10 + i], s);
            float xph = fmaxf(s, 0.f);
            float xlh = dpl[j] * al + xu[j] * au;
            float s3 = 0.f;
#pragma unroll
            for (int i = 0; i < 10; i++) s3 = fmaf(xfv[i], sw[SB + O_DUW + j * 10 + i], s3);
            float xfh = fmaxf(attu * s3, 0.f);
            m[j] = xph + xlh + xfh;
        }
#pragma unroll
        for (int j = 0; j < 10; j++) {
            float g = sw[SB + O_GUB + j], cd = 0.f;
#pragma unroll
            for (int i = 0; i < 10; i++) {
                g  = fmaf(xu[i], sw[SB + O_GUW + j * 20 + i], g);
                cd = fmaf(xu[i], sw[SB + O_CDUW + j * 20 + i], cd);
            }
#pragma unroll
            for (int i = 0; i < 10; i++) {
                g  = fmaf(m[i], sw[SB + O_GUW + j * 20 + 10 + i], g);
                cd = fmaf(m[i], sw[SB + O_CDUW + j * 20 + 10 + i], cd);
            }
            g = sig1(g);
            cd = fmaxf(cd, 0.f);
            out[(n * 10 + j) * HW + pp] = fmaf(g, cd - xu[j], xu[j]);
        }
        out[OUT_ATTU + n * HW + pp] = attu;
    }

    // =================== L branch ===================
    {
        float msg0 = 0.f, msg1 = 0.f, msg2 = 0.f, msg3 = 0.f, msg4 = 0.f,
              msg5 = 0.f, msg6 = 0.f, msg7 = 0.f, msg8 = 0.f, msg9 = 0.f;
#pragma unroll
        for (int p = 0; p < 2; p++) {
            float ca = sw[SB + O_CLAB + p];
            float pv[10];
#pragma unroll
            for (int i = 0; i < 10; i++) {
                pv[i] = xp[(((p + 4) * NB + n) * 10 + i) * HW + pp];
                ca = fmaf(pv[i], sw[SB + O_CLAW + p * 10 + i], ca);
            }
            ca = sig1(ca);
            msg0 = fmaf(pv[0], ca, msg0); msg1 = fmaf(pv[1], ca, msg1);
            msg2 = fmaf(pv[2], ca, msg2); msg3 = fmaf(pv[3], ca, msg3);
            msg4 = fmaf(pv[4], ca, msg4); msg5 = fmaf(pv[5], ca, msg5);
            msg6 = fmaf(pv[6], ca, msg6); msg7 = fmaf(pv[7], ca, msg7);
            msg8 = fmaf(pv[8], ca, msg8); msg9 = fmaf(pv[9], ca, msg9);
        }
        float msg[10] = {msg0, msg1, msg2, msg3, msg4, msg5, msg6, msg7, msg8, msg9};
#pragma unroll
        for (int j = 0; j < 10; j++) {
            float s = 0.f;
#pragma unroll
            for (int i = 0; i < 10; i++) s = fmaf(xl[i],  sw[SB + O_CLW + j * 20 + i], s);
#pragma unroll
            for (int i = 0; i < 10; i++) s = fmaf(msg[i], sw[SB + O_CLW + j * 20 + 10 + i], s);
            float xph = fmaxf(s, 0.f);
            float xuh = dpu[j] * au + xl[j] * al;
            float s3 = 0.f;
#pragma unroll
            for (int i = 0; i < 10; i++) s3 = fmaf(xfv[i], sw[SB + O_DLW + j * 10 + i], s3);
            float xfh = fmaxf(attl * s3, 0.f);
            m[j] = xph + xuh + xfh;
        }
#pragma unroll
        for (int j = 0; j < 10; j++) {
            float g = sw[SB + O_GLB + j], cd = 0.f;
#pragma unroll
            for (int i = 0; i < 10; i++) {
                g  = fmaf(xl[i], sw[SB + O_GLW + j * 20 + i], g);
                cd = fmaf(xl[i], sw[SB + O_CDLW + j * 20 + i], cd);
            }
#pragma unroll
            for (int i = 0; i < 10; i++) {
                g  = fmaf(m[i], sw[SB + O_GLW + j * 20 + 10 + i], g);
                cd = fmaf(m[i], sw[SB + O_CDLW + j * 20 + 10 + i], cd);
            }
            g = sig1(g);
            cd = fmaxf(cd, 0.f);
            out[OUT_XHL + (n * 10 + j) * HW + pp] = fmaf(g, cd - xl[j], xl[j]);
        }
        out[OUT_ATTL + n * HW + pp] = attl;
    }
}

extern "C" void kernel_launch(void* const* d_in, const int* in_sizes, int n_in,
                              void* d_out, int out_size)
{
    k1_main<<<1024, 128>>>(
        (const float*)d_in[0],   // h_fea
        (const float*)d_in[5],   // pdp_w1
        (const float*)d_in[15],  // decU_att_w
        (const float*)d_in[18]); // decL_att_w

    k2_post<<<1024, 128>>>(
        (const float*)d_in[1],  (const float*)d_in[2],
        (const float*)d_in[3],  (const float*)d_in[4],
        (const float*)d_in[5],  (const float*)d_in[6],
        (const float*)d_in[7],  (const float*)d_in[8],
        (const float*)d_in[9],  (const float*)d_in[10], (const float*)d_in[11],
        (const float*)d_in[12], (const float*)d_in[13], (const float*)d_in[14],
        (const float*)d_in[15], (const float*)d_in[16], (const float*)d_in[17],
        (const float*)d_in[18], (const float*)d_in[19], (const float*)d_in[20],
        (const float*)d_in[21], (const float*)d_in[22], (const float*)d_in[23],
        (const float*)d_in[24], (const float*)d_in[25], (const float*)d_in[26],
        (float*)d_out);
}

// round 7
// speedup vs baseline: 1.1747x; 1.1747x over previous
#include <cuda_runtime.h>

#define HW   16384      // 128*128
#define NCH  256
#define NB   8
#define PAIRS 65536     // 131072 pixels / 2
#define NPIX 131072

typedef unsigned long long u64;

// ---------------- packed f32x2 helpers (sm_103a) ----------------
__device__ __forceinline__ u64 fma2(u64 a, u64 b, u64 c) {
    u64 d; asm("fma.rn.f32x2 %0,%1,%2,%3;" : "=l"(d) : "l"(a), "l"(b), "l"(c)); return d;
}
__device__ __forceinline__ u64 pk2(float x, float y) {
    u64 r; asm("mov.b64 %0,{%1,%2};" : "=l"(r) : "f"(x), "f"(y)); return r;
}
__device__ __forceinline__ float sig1(float x) {
    return __fdividef(1.f, 1.f + __expf(-x));
}

// Partial dot products: [chalf][o][pair], u64 = 2 px. K2 sums the 2 halves.
__device__ u64 g_scratch[2 * 22 * PAIRS];

// Output offsets (tuple flattened: xh_u_new, xh_l_new, att_u, att_l)
#define OUT_XHL  1310720
#define OUT_ATTU 2621440
#define OUT_ATTL 2752512

// =========================================================================
// Kernel 1: [px x 256] @ [256 x 22] streaming GEMM over h_fea.
// CHANNEL-split: 2 threads per pixel-pair, 128 channels each, 22 partial
// accumulators per thread. Register double-buffer pipeline, MLP = 8.
// Block = 128 thr: warps 0-1 do chalf 0 for 64 pairs, warps 2-3 chalf 1.
// =========================================================================
__global__ __launch_bounds__(128, 4) void k1_main(
    const float* __restrict__ h_fea,
    const float* __restrict__ pdp_w1,
    const float* __restrict__ dU_aw,
    const float* __restrict__ dL_aw)
{
    __shared__ u64 swk[256 * 22];           // 45056 B
    const int tid = threadIdx.x;

    for (int idx = tid; idx < 256 * 22; idx += 128) {
        int c = idx / 22, o = idx - c * 22;
        float v = (o < 20) ? pdp_w1[o * 276 + c] : ((o == 20) ? dU_aw[c] : dL_aw[c]);
        swk[idx] = pk2(v, v);
    }
    __syncthreads();

    const int pair  = blockIdx.x * 64 + (tid & 63);
    const int chalf = tid >> 6;                 // 0: c in [0,128), 1: [128,256)
    const int ch0   = chalf * 128;
    const int P  = pair * 2;
    const int n  = P >> 14;                     // 8192 pairs per image; 64 | 8192
    const int pp = P & (HW - 1);
    const float* hb = h_fea + n * (NCH * HW) + ch0 * HW + pp;

    u64 acc[22];
#pragma unroll
    for (int o = 0; o < 22; o++) acc[o] = 0ull;

    u64 bA[8], bB[8];

#define LOAD_CHUNK(B, C0)                                                     \
    _Pragma("unroll")                                                         \
    for (int j = 0; j < 8; j++)                                               \
        B[j] = *reinterpret_cast<const u64*>(hb + ((C0) + j) * HW);

#define COMP_CHUNK(B, C0)                                                     \
    _Pragma("unroll")                                                         \
    for (int j = 0; j < 8; j++) {                                             \
        u64 xx = B[j];                                                        \
        const ulonglong2* w = reinterpret_cast<const ulonglong2*>(            \
            &swk[(ch0 + (C0) + j) * 22]);                                     \
        _Pragma("unroll")                                                     \
        for (int o = 0; o < 11; o++) {                                        \
            ulonglong2 wv = w[o];                                             \
            acc[2 * o]     = fma2(xx, wv.x, acc[2 * o]);                      \
            acc[2 * o + 1] = fma2(xx, wv.y, acc[2 * o + 1]);                  \
        }                                                                     \
    }

    LOAD_CHUNK(bA, 0)
#pragma unroll 1
    for (int c0 = 0; c0 < 128; c0 += 16) {
        LOAD_CHUNK(bB, c0 + 8)
        COMP_CHUNK(bA, c0)
        const int nxt = (c0 + 16) & 127;      // last iter reloads chunk 0 (dead)
        LOAD_CHUNK(bA, nxt)
        COMP_CHUNK(bB, c0 + 8)
    }
#undef LOAD_CHUNK
#undef COMP_CHUNK

    u64* dst = g_scratch + chalf * (22 * PAIRS) + pair;
#pragma unroll
    for (int o = 0; o < 22; o++)
        dst[o * PAIRS] = acc[o];
}

// =========================================================================
// Kernel 2: tails + graph logic — SCALAR, 1 pixel/thread.
// (identical to R4/R6 except acc = sum of the two channel-half partials)
// =========================================================================
#define SB 440
#define O_W2    0
#define O_ATTW  200
#define O_ATTB  220
#define O_CUAW  222
#define O_CUAB  262
#define O_CUW   266
#define O_CLAW  466
#define O_CLAB  486
#define O_CLW   488
#define O_DUB   688
#define O_DUW   689
#define O_DLB   789
#define O_DLW   790
#define O_GUW   890
#define O_GUB   1090
#define O_CDUW  1100
#define O_GLW   1300
#define O_GLB   1500
#define O_CDLW  1510
#define SM2_F32 (SB + 1710)

__global__ __launch_bounds__(128, 4) void k2_post(
    const float* __restrict__ xh_u, const float* __restrict__ xh_l,
    const float* __restrict__ xf, const float* __restrict__ xp,
    const float* __restrict__ pdp_w1, const float* __restrict__ pdp_w2,
    const float* __restrict__ att_w, const float* __restrict__ att_b,
    const float* __restrict__ cU_aw, const float* __restrict__ cU_ab, const float* __restrict__ cU_w,
    const float* __restrict__ cL_aw, const float* __restrict__ cL_ab, const float* __restrict__ cL_w,
    const float* __restrict__ dU_aw, const float* __restrict__ dU_ab, const float* __restrict__ dU_w,
    const float* __restrict__ dL_aw, const float* __restrict__ dL_ab, const float* __restrict__ dL_w,
    const float* __restrict__ gU_w, const float* __restrict__ gU_b, const float* __restrict__ cdU_w,
    const float* __restrict__ gL_w, const float* __restrict__ gL_b, const float* __restrict__ cdL_w,
    float* __restrict__ out)
{
    __shared__ float sw[SM2_F32];           // 8.6 KB
    const int tid = threadIdx.x;

    for (int idx = tid; idx < 400; idx += 128) {
        int o = idx / 20, i = idx - o * 20;
        sw[idx] = pdp_w1[o * 276 + 256 + i];      // cat [h_fea, xh_u, xh_l]
    }
    if (tid < 20) {
        sw[400 + tid] = dU_aw[256 + tid];         // [h_fea, xf, xh_u]
        sw[420 + tid] = dL_aw[256 + tid];         // [h_fea, xf, xh_l]
    }
#define CPY(src, n_, off) for (int j = tid; j < (n_); j += 128) sw[SB + (off) + j] = (src)[j];
    CPY(pdp_w2, 200, O_W2)
    CPY(att_w, 20, O_ATTW)
    CPY(att_b, 2, O_ATTB)
    CPY(cU_aw, 40, O_CUAW)
    CPY(cU_ab, 4, O_CUAB)
    CPY(cU_w, 200, O_CUW)
    CPY(cL_aw, 20, O_CLAW)
    CPY(cL_ab, 2, O_CLAB)
    CPY(cL_w, 200, O_CLW)
    CPY(dU_ab, 1, O_DUB)
    CPY(dU_w, 100, O_DUW)
    CPY(dL_ab, 1, O_DLB)
    CPY(dL_w, 100, O_DLW)
    CPY(gU_w, 200, O_GUW)
    CPY(gU_b, 10, O_GUB)
    CPY(cdU_w, 200, O_CDUW)
    CPY(gL_w, 200, O_GLW)
    CPY(gL_b, 10, O_GLB)
    CPY(cdL_w, 200, O_CDLW)
#undef CPY
    __syncthreads();

    const int P  = blockIdx.x * 128 + tid;  // one pixel per thread
    const int n  = P >> 14;
    const int pp = P & (HW - 1);

    const float* gsf = reinterpret_cast<const float*>(g_scratch);

    float acc[22];
#pragma unroll
    for (int o = 0; o < 22; o++)
        acc[o] = gsf[o * NPIX + P] + gsf[22 * NPIX + o * NPIX + P];

    const int base10 = n * 10 * HW + pp;
    float xu[10], xl[10], xfv[10];
#pragma unroll
    for (int i = 0; i < 10; i++) {
        xu[i]  = xh_u[base10 + i * HW];
        xl[i]  = xh_l[base10 + i * HW];
        xfv[i] = xf[base10 + i * HW];
    }

    // tails of the 276-channel dot products
#pragma unroll
    for (int o = 0; o < 20; o++) {
        float a = acc[o];
#pragma unroll
        for (int i = 0; i < 10; i++) {
            a = fmaf(xu[i], sw[o * 20 + i], a);
            a = fmaf(xl[i], sw[o * 20 + 10 + i], a);
        }
        acc[o] = a;
    }
    {
        float a = acc[20];
#pragma unroll
        for (int i = 0; i < 10; i++) {
            a = fmaf(xfv[i], sw[400 + i], a);
            a = fmaf(xu[i],  sw[410 + i], a);
        }
        acc[20] = a;
        float b = acc[21];
#pragma unroll
        for (int i = 0; i < 10; i++) {
            b = fmaf(xfv[i], sw[420 + i], b);
            b = fmaf(xl[i],  sw[430 + i], b);
        }
        acc[21] = b;
    }

    const float attu = sig1(acc[20] + sw[SB + O_DUB]);
    const float attl = sig1(acc[21] + sw[SB + O_DLB]);

#pragma unroll
    for (int o = 0; o < 20; o++) acc[o] = fmaxf(acc[o], 0.f);

    // dp grouped 10x10
    float dpu[10], dpl[10];
#pragma unroll
    for (int j = 0; j < 10; j++) {
        float s = 0.f, s2 = 0.f;
#pragma unroll
        for (int i = 0; i < 10; i++) {
            s  = fmaf(acc[i],      sw[SB + O_W2 + j * 10 + i], s);
            s2 = fmaf(acc[10 + i], sw[SB + O_W2 + 100 + j * 10 + i], s2);
        }
        dpu[j] = fmaxf(s, 0.f);
        dpl[j] = fmaxf(s2, 0.f);
    }

    // grouped gate attention
    float au = sw[SB + O_ATTB + 0], al = sw[SB + O_ATTB + 1];
#pragma unroll
    for (int i = 0; i < 10; i++) {
        au = fmaf(xu[i], sw[SB + O_ATTW + i], au);
        al = fmaf(xl[i], sw[SB + O_ATTW + 10 + i], al);
    }
    au = sig1(au);
    al = sig1(al);

    float m[10];

    // =================== U branch ===================
    {
        float msg0 = 0.f, msg1 = 0.f, msg2 = 0.f, msg3 = 0.f, msg4 = 0.f,
              msg5 = 0.f, msg6 = 0.f, msg7 = 0.f, msg8 = 0.f, msg9 = 0.f;
#pragma unroll
        for (int p = 0; p < 4; p++) {
            float ca = sw[SB + O_CUAB + p];
            float pv[10];
#pragma unroll
            for (int i = 0; i < 10; i++) {
                pv[i] = xp[((p * NB + n) * 10 + i) * HW + pp];
                ca = fmaf(pv[i], sw[SB + O_CUAW + p * 10 + i], ca);
            }
            ca = sig1(ca);
            msg0 = fmaf(pv[0], ca, msg0); msg1 = fmaf(pv[1], ca, msg1);
            msg2 = fmaf(pv[2], ca, msg2); msg3 = fmaf(pv[3], ca, msg3);
            msg4 = fmaf(pv[4], ca, msg4); msg5 = fmaf(pv[5], ca, msg5);
            msg6 = fmaf(pv[6], ca, msg6); msg7 = fmaf(pv[7], ca, msg7);
            msg8 = fmaf(pv[8], ca, msg8); msg9 = fmaf(pv[9], ca, msg9);
        }
        float msg[10] = {msg0, msg1, msg2, msg3, msg4, msg5, msg6, msg7, msg8, msg9};
#pragma unroll
        for (int j = 0; j < 10; j++) {
            float s = 0.f;
#pragma unroll
            for (int i = 0; i < 10; i++) s = fmaf(xu[i],  sw[SB + O_CUW + j * 20 + i], s);
#pragma unroll
            for (int i = 0; i < 10; i++) s = fmaf(msg[i], sw[SB + O_CUW + j * 20 + 10 + i], s);
            float xph = fmaxf(s, 0.f);
            float xlh = dpl[j] * al + xu[j] * au;
            float s3 = 0.f;
#pragma unroll
            for (int i = 0; i < 10; i++) s3 = fmaf(xfv[i], sw[SB + O_DUW + j * 10 + i], s3);
            float xfh = fmaxf(attu * s3, 0.f);
            m[j] = xph + xlh + xfh;
        }
#pragma unroll
        for (int j = 0; j < 10; j++) {
            float g = sw[SB + O_GUB + j], cd = 0.f;
#pragma unroll
            for (int i = 0; i < 10; i++) {
                g  = fmaf(xu[i], sw[SB + O_GUW + j * 20 + i], g);
                cd = fmaf(xu[i], sw[SB + O_CDUW + j * 20 + i], cd);
            }
#pragma unroll
            for (int i = 0; i < 10; i++) {
                g  = fmaf(m[i], sw[SB + O_GUW + j * 20 + 10 + i], g);
                cd = fmaf(m[i], sw[SB + O_CDUW + j * 20 + 10 + i], cd);
            }
            g = sig1(g);
            cd = fmaxf(cd, 0.f);
            out[(n * 10 + j) * HW + pp] = fmaf(g, cd - xu[j], xu[j]);
        }
        out[OUT_ATTU + n * HW + pp] = attu;
    }

    // =================== L branch ===================
    {
        float msg0 = 0.f, msg1 = 0.f, msg2 = 0.f, msg3 = 0.f, msg4 = 0.f,
              msg5 = 0.f, msg6 = 0.f, msg7 = 0.f, msg8 = 0.f, msg9 = 0.f;
#pragma unroll
        for (int p = 0; p < 2; p++) {
            float ca = sw[SB + O_CLAB + p];
            float pv[10];
#pragma unroll
            for (int i = 0; i < 10; i++) {
                pv[i] = xp[(((p + 4) * NB + n) * 10 + i) * HW + pp];
                ca = fmaf(pv[i], sw[SB + O_CLAW + p * 10 + i], ca);
            }
            ca = sig1(ca);
            msg0 = fmaf(pv[0], ca, msg0); msg1 = fmaf(pv[1], ca, msg1);
            msg2 = fmaf(pv[2], ca, msg2); msg3 = fmaf(pv[3], ca, msg3);
            msg4 = fmaf(pv[4], ca, msg4); msg5 = fmaf(pv[5], ca, msg5);
            msg6 = fmaf(pv[6], ca, msg6); msg7 = fmaf(pv[7], ca, msg7);
            msg8 = fmaf(pv[8], ca, msg8); msg9 = fmaf(pv[9], ca, msg9);
        }
        float msg[10] = {msg0, msg1, msg2, msg3, msg4, msg5, msg6, msg7, msg8, msg9};
#pragma unroll
        for (int j = 0; j < 10; j++) {
            float s = 0.f;
#pragma unroll
            for (int i = 0; i < 10; i++) s = fmaf(xl[i],  sw[SB + O_CLW + j * 20 + i], s);
#pragma unroll
            for (int i = 0; i < 10; i++) s = fmaf(msg[i], sw[SB + O_CLW + j * 20 + 10 + i], s);
            float xph = fmaxf(s, 0.f);
            float xuh = dpu[j] * au + xl[j] * al;
            float s3 = 0.f;
#pragma unroll
            for (int i = 0; i < 10; i++) s3 = fmaf(xfv[i], sw[SB + O_DLW + j * 10 + i], s3);
            float xfh = fmaxf(attl * s3, 0.f);
            m[j] = xph + xuh + xfh;
        }
#pragma unroll
        for (int j = 0; j < 10; j++) {
            float g = sw[SB + O_GLB + j], cd = 0.f;
#pragma unroll
            for (int i = 0; i < 10; i++) {
                g  = fmaf(xl[i], sw[SB + O_GLW + j * 20 + i], g);
                cd = fmaf(xl[i], sw[SB + O_CDLW + j * 20 + i], cd);
            }
#pragma unroll
            for (int i = 0; i < 10; i++) {
                g  = fmaf(m[i], sw[SB + O_GLW + j * 20 + 10 + i], g);
                cd = fmaf(m[i], sw[SB + O_CDLW + j * 20 + 10 + i], cd);
            }
            g = sig1(g);
            cd = fmaxf(cd, 0.f);
            out[OUT_XHL + (n * 10 + j) * HW + pp] = fmaf(g, cd - xl[j], xl[j]);
        }
        out[OUT_ATTL + n * HW + pp] = attl;
    }
}

extern "C" void kernel_launch(void* const* d_in, const int* in_sizes, int n_in,
                              void* d_out, int out_size)
{
    k1_main<<<1024, 128>>>(
        (const float*)d_in[0],   // h_fea
        (const float*)d_in[5],   // pdp_w1
        (const float*)d_in[15],  // decU_att_w
        (const float*)d_in[18]); // decL_att_w

    k2_post<<<1024, 128>>>(
        (const float*)d_in[1],  (const float*)d_in[2],
        (const float*)d_in[3],  (const float*)d_in[4],
        (const float*)d_in[5],  (const float*)d_in[6],
        (const float*)d_in[7],  (const float*)d_in[8],
        (const float*)d_in[9],  (const float*)d_in[10], (const float*)d_in[11],
        (const float*)d_in[12], (const float*)d_in[13], (const float*)d_in[14],
        (const float*)d_in[15], (const float*)d_in[16], (const float*)d_in[17],
        (const float*)d_in[18], (const float*)d_in[19], (const float*)d_in[20],
        (const float*)d_in[21], (const float*)d_in[22], (const float*)d_in[23],
        (const float*)d_in[24], (const float*)d_in[25], (const float*)d_in[26],
        (float*)d_out);
}

// round 8
// speedup vs baseline: 1.1773x; 1.0023x over previous
#include <cuda_runtime.h>

#define HW   16384      // 128*128
#define NCH  256
#define NB   8
#define PAIRS 65536     // 131072 pixels / 2
#define NPIX 131072

typedef unsigned long long u64;

// ---------------- packed f32x2 helpers (sm_103a) ----------------
__device__ __forceinline__ u64 fma2(u64 a, u64 b, u64 c) {
    u64 d; asm("fma.rn.f32x2 %0,%1,%2,%3;" : "=l"(d) : "l"(a), "l"(b), "l"(c)); return d;
}
__device__ __forceinline__ u64 pk2(float x, float y) {
    u64 r; asm("mov.b64 %0,{%1,%2};" : "=l"(r) : "f"(x), "f"(y)); return r;
}
__device__ __forceinline__ float sig1(float x) {
    return __fdividef(1.f, 1.f + __expf(-x));
}
__device__ __forceinline__ void pref_l2(const void* p) {
    asm volatile("prefetch.global.L2 [%0];" :: "l"(p));
}

// 22 partial dot products per pixel-pair, [o][pairIdx] layout (u64 = 2 px)
__device__ u64 g_scratch[22 * PAIRS];

// Output offsets (tuple flattened: xh_u_new, xh_l_new, att_u, att_l)
#define OUT_XHL  1310720
#define OUT_ATTU 2621440
#define OUT_ATTL 2752512

// =========================================================================
// Kernel 1: [px x 256] @ [256 x 22] streaming GEMM over h_fea.
// Register double-buffer software pipeline (MLP=8) + L2 prefetch 48
// channels (~600+ cyc) ahead so LDGs land in L2 instead of DRAM.
// =========================================================================
__global__ __launch_bounds__(128, 4) void k1_main(
    const float* __restrict__ h_fea,
    const float* __restrict__ pdp_w1,
    const float* __restrict__ dU_aw,
    const float* __restrict__ dL_aw)
{
    __shared__ u64 swk[256 * 22];           // 45056 B
    const int tid = threadIdx.x;

    for (int idx = tid; idx < 256 * 22; idx += 128) {
        int c = idx / 22, o = idx - c * 22;
        float v = (o < 20) ? pdp_w1[o * 276 + c] : ((o == 20) ? dU_aw[c] : dL_aw[c]);
        swk[idx] = pk2(v, v);
    }
    __syncthreads();

    const int pair = blockIdx.x * 128 + tid;
    const int P  = pair * 2;
    const int n  = P >> 14;
    const int pp = P & (HW - 1);
    const float* hb = h_fea + n * (NCH * HW) + pp;

    u64 acc[22];
#pragma unroll
    for (int o = 0; o < 22; o++) acc[o] = 0ull;

    u64 bA[8], bB[8];

#define LOAD_CHUNK(B, C0)                                                     \
    _Pragma("unroll")                                                         \
    for (int j = 0; j < 8; j++)                                               \
        B[j] = *reinterpret_cast<const u64*>(hb + ((C0) + j) * HW);

#define PREF_CHUNK(C0)                                                        \
    _Pragma("unroll")                                                         \
    for (int j = 0; j < 16; j++)                                              \
        pref_l2(hb + ((((C0) + j) & 255)) * HW);

#define COMP_CHUNK(B, C0)                                                     \
    _Pragma("unroll")                                                         \
    for (int j = 0; j < 8; j++) {                                             \
        u64 xx = B[j];                                                        \
        const ulonglong2* w =                                                 \
            reinterpret_cast<const ulonglong2*>(&swk[((C0) + j) * 22]);       \
        _Pragma("unroll")                                                     \
        for (int o = 0; o < 11; o++) {                                        \
            ulonglong2 wv = w[o];                                             \
            acc[2 * o]     = fma2(xx, wv.x, acc[2 * o]);                      \
            acc[2 * o + 1] = fma2(xx, wv.y, acc[2 * o + 1]);                  \
        }                                                                     \
    }

    // prefetch the first 48 channels before the pipeline starts
    PREF_CHUNK(0)
    PREF_CHUNK(16)
    PREF_CHUNK(32)

    LOAD_CHUNK(bA, 0)
#pragma unroll 1
    for (int c0 = 0; c0 < 256; c0 += 16) {
        LOAD_CHUNK(bB, c0 + 8)
        PREF_CHUNK(c0 + 48)                   // ~3 macro-iters (~600+ cyc) ahead
        COMP_CHUNK(bA, c0)
        const int nxt = (c0 + 16) & 255;      // last iter reloads chunk 0 (dead)
        LOAD_CHUNK(bA, nxt)
        COMP_CHUNK(bB, c0 + 8)
    }
#undef LOAD_CHUNK
#undef PREF_CHUNK
#undef COMP_CHUNK

#pragma unroll
    for (int o = 0; o < 22; o++)
        g_scratch[o * PAIRS + pair] = acc[o];
}

// =========================================================================
// Kernel 2: tails + graph logic — SCALAR, 1 pixel/thread. (R4-identical)
// =========================================================================
#define SB 440
#define O_W2    0
#define O_ATTW  200
#define O_ATTB  220
#define O_CUAW  222
#define O_CUAB  262
#define O_CUW   266
#define O_CLAW  466
#define O_CLAB  486
#define O_CLW   488
#define O_DUB   688
#define O_DUW   689
#define O_DLB   789
#define O_DLW   790
#define O_GUW   890
#define O_GUB   1090
#define O_CDUW  1100
#define O_GLW   1300
#define O_GLB   1500
#define O_CDLW  1510
#define SM2_F32 (SB + 1710)

__global__ __launch_bounds__(128, 4) void k2_post(
    const float* __restrict__ xh_u, const float* __restrict__ xh_l,
    const float* __restrict__ xf, const float* __restrict__ xp,
    const float* __restrict__ pdp_w1, const float* __restrict__ pdp_w2,
    const float* __restrict__ att_w, const float* __restrict__ att_b,
    const float* __restrict__ cU_aw, const float* __restrict__ cU_ab, const float* __restrict__ cU_w,
    const float* __restrict__ cL_aw, const float* __restrict__ cL_ab, const float* __restrict__ cL_w,
    const float* __restrict__ dU_aw, const float* __restrict__ dU_ab, const float* __restrict__ dU_w,
    const float* __restrict__ dL_aw, const float* __restrict__ dL_ab, const float* __restrict__ dL_w,
    const float* __restrict__ gU_w, const float* __restrict__ gU_b, const float* __restrict__ cdU_w,
    const float* __restrict__ gL_w, const float* __restrict__ gL_b, const float* __restrict__ cdL_w,
    float* __restrict__ out)
{
    __shared__ float sw[SM2_F32];           // 8.6 KB
    const int tid = threadIdx.x;

    for (int idx = tid; idx < 400; idx += 128) {
        int o = idx / 20, i = idx - o * 20;
        sw[idx] = pdp_w1[o * 276 + 256 + i];      // cat [h_fea, xh_u, xh_l]
    }
    if (tid < 20) {
        sw[400 + tid] = dU_aw[256 + tid];         // [h_fea, xf, xh_u]
        sw[420 + tid] = dL_aw[256 + tid];         // [h_fea, xf, xh_l]
    }
#define CPY(src, n_, off) for (int j = tid; j < (n_); j += 128) sw[SB + (off) + j] = (src)[j];
    CPY(pdp_w2, 200, O_W2)
    CPY(att_w, 20, O_ATTW)
    CPY(att_b, 2, O_ATTB)
    CPY(cU_aw, 40, O_CUAW)
    CPY(cU_ab, 4, O_CUAB)
    CPY(cU_w, 200, O_CUW)
    CPY(cL_aw, 20, O_CLAW)
    CPY(cL_ab, 2, O_CLAB)
    CPY(cL_w, 200, O_CLW)
    CPY(dU_ab, 1, O_DUB)
    CPY(dU_w, 100, O_DUW)
    CPY(dL_ab, 1, O_DLB)
    CPY(dL_w, 100, O_DLW)
    CPY(gU_w, 200, O_GUW)
    CPY(gU_b, 10, O_GUB)
    CPY(cdU_w, 200, O_CDUW)
    CPY(gL_w, 200, O_GLW)
    CPY(gL_b, 10, O_GLB)
    CPY(cdL_w, 200, O_CDLW)
#undef CPY
    __syncthreads();

    const int P  = blockIdx.x * 128 + tid;  // one pixel per thread
    const int n  = P >> 14;
    const int pp = P & (HW - 1);

    const float* gsf = reinterpret_cast<const float*>(g_scratch);

    float acc[22];
#pragma unroll
    for (int o = 0; o < 22; o++) acc[o] = gsf[o * NPIX + P];

    const int base10 = n * 10 * HW + pp;
    float xu[10], xl[10], xfv[10];
#pragma unroll
    for (int i = 0; i < 10; i++) {
        xu[i]  = xh_u[base10 + i * HW];
        xl[i]  = xh_l[base10 + i * HW];
        xfv[i] = xf[base10 + i * HW];
    }

    // tails of the 276-channel dot products
#pragma unroll
    for (int o = 0; o < 20; o++) {
        float a = acc[o];
#pragma unroll
        for (int i = 0; i < 10; i++) {
            a = fmaf(xu[i], sw[o * 20 + i], a);
            a = fmaf(xl[i], sw[o * 20 + 10 + i], a);
        }
        acc[o] = a;
    }
    {
        float a = acc[20];
#pragma unroll
        for (int i = 0; i < 10; i++) {
            a = fmaf(xfv[i], sw[400 + i], a);
            a = fmaf(xu[i],  sw[410 + i], a);
        }
        acc[20] = a;
        float b = acc[21];
#pragma unroll
        for (int i = 0; i < 10; i++) {
            b = fmaf(xfv[i], sw[420 + i], b);
            b = fmaf(xl[i],  sw[430 + i], b);
        }
        acc[21] = b;
    }

    const float attu = sig1(acc[20] + sw[SB + O_DUB]);
    const float attl = sig1(acc[21] + sw[SB + O_DLB]);

#pragma unroll
    for (int o = 0; o < 20; o++) acc[o] = fmaxf(acc[o], 0.f);

    // dp grouped 10x10
    float dpu[10], dpl[10];
#pragma unroll
    for (int j = 0; j < 10; j++) {
        float s = 0.f, s2 = 0.f;
#pragma unroll
        for (int i = 0; i < 10; i++) {
            s  = fmaf(acc[i],      sw[SB + O_W2 + j * 10 + i], s);
            s2 = fmaf(acc[10 + i], sw[SB + O_W2 + 100 + j * 10 + i], s2);
        }
        dpu[j] = fmaxf(s, 0.f);
        dpl[j] = fmaxf(s2, 0.f);
    }

    // grouped gate attention
    float au = sw[SB + O_ATTB + 0], al = sw[SB + O_ATTB + 1];
#pragma unroll
    for (int i = 0; i < 10; i++) {
        au = fmaf(xu[i], sw[SB + O_ATTW + i], au);
        al = fmaf(xl[i], sw[SB + O_ATTW + 10 + i], al);
    }
    au = sig1(au);
    al = sig1(al);

    float m[10];

    // =================== U branch ===================
    {
        float msg0 = 0.f, msg1 = 0.f, msg2 = 0.f, msg3 = 0.f, msg4 = 0.f,
              msg5 = 0.f, msg6 = 0.f, msg7 = 0.f, msg8 = 0.f, msg9 = 0.f;
#pragma unroll
        for (int p = 0; p < 4; p++) {
            float ca = sw[SB + O_CUAB + p];
            float pv[10];
#pragma unroll
            for (int i = 0; i < 10; i++) {
                pv[i] = xp[((p * NB + n) * 10 + i) * HW + pp];
                ca = fmaf(pv[i], sw[SB + O_CUAW + p * 10 + i], ca);
            }
            ca = sig1(ca);
            msg0 = fmaf(pv[0], ca, msg0); msg1 = fmaf(pv[1], ca, msg1);
            msg2 = fmaf(pv[2], ca, msg2); msg3 = fmaf(pv[3], ca, msg3);
            msg4 = fmaf(pv[4], ca, msg4); msg5 = fmaf(pv[5], ca, msg5);
            msg6 = fmaf(pv[6], ca, msg6); msg7 = fmaf(pv[7], ca, msg7);
            msg8 = fmaf(pv[8], ca, msg8); msg9 = fmaf(pv[9], ca, msg9);
        }
        float msg[10] = {msg0, msg1, msg2, msg3, msg4, msg5, msg6, msg7, msg8, msg9};
#pragma unroll
        for (int j = 0; j < 10; j++) {
            float s = 0.f;
#pragma unroll
            for (int i = 0; i < 10; i++) s = fmaf(xu[i],  sw[SB + O_CUW + j * 20 + i], s);
#pragma unroll
            for (int i = 0; i < 10; i++) s = fmaf(msg[i], sw[SB + O_CUW + j * 20 + 10 + i], s);
            float xph = fmaxf(s, 0.f);
            float xlh = dpl[j] * al + xu[j] * au;
            float s3 = 0.f;
#pragma unroll
            for (int i = 0; i < 10; i++) s3 = fmaf(xfv[i], sw[SB + O_DUW + j * 10 + i], s3);
            float xfh = fmaxf(attu * s3, 0.f);
            m[j] = xph + xlh + xfh;
        }
#pragma unroll
        for (int j = 0; j < 10; j++) {
            float g = sw[SB + O_GUB + j], cd = 0.f;
#pragma unroll
            for (int i = 0; i < 10; i++) {
                g  = fmaf(xu[i], sw[SB + O_GUW + j * 20 + i], g);
                cd = fmaf(xu[i], sw[SB + O_CDUW + j * 20 + i], cd);
            }
#pragma unroll
            for (int i = 0; i < 10; i++) {
                g  = fmaf(m[i], sw[SB + O_GUW + j * 20 + 10 + i], g);
                cd = fmaf(m[i], sw[SB + O_CDUW + j * 20 + 10 + i], cd);
            }
            g = sig1(g);
            cd = fmaxf(cd, 0.f);
            out[(n * 10 + j) * HW + pp] = fmaf(g, cd - xu[j], xu[j]);
        }
        out[OUT_ATTU + n * HW + pp] = attu;
    }

    // =================== L branch ===================
    {
        float msg0 = 0.f, msg1 = 0.f, msg2 = 0.f, msg3 = 0.f, msg4 = 0.f,
              msg5 = 0.f, msg6 = 0.f, msg7 = 0.f, msg8 = 0.f, msg9 = 0.f;
#pragma unroll
        for (int p = 0; p < 2; p++) {
            float ca = sw[SB + O_CLAB + p];
            float pv[10];
#pragma unroll
            for (int i = 0; i < 10; i++) {
                pv[i] = xp[(((p + 4) * NB + n) * 10 + i) * HW + pp];
                ca = fmaf(pv[i], sw[SB + O_CLAW + p * 10 + i], ca);
            }
            ca = sig1(ca);
            msg0 = fmaf(pv[0], ca, msg0); msg1 = fmaf(pv[1], ca, msg1);
            msg2 = fmaf(pv[2], ca, msg2); msg3 = fmaf(pv[3], ca, msg3);
            msg4 = fmaf(pv[4], ca, msg4); msg5 = fmaf(pv[5], ca, msg5);
            msg6 = fmaf(pv[6], ca, msg6); msg7 = fmaf(pv[7], ca, msg7);
            msg8 = fmaf(pv[8], ca, msg8); msg9 = fmaf(pv[9], ca, msg9);
        }
        float msg[10] = {msg0, msg1, msg2, msg3, msg4, msg5, msg6, msg7, msg8, msg9};
#pragma unroll
        for (int j = 0; j < 10; j++) {
            float s = 0.f;
#pragma unroll
            for (int i = 0; i < 10; i++) s = fmaf(xl[i],  sw[SB + O_CLW + j * 20 + i], s);
#pragma unroll
            for (int i = 0; i < 10; i++) s = fmaf(msg[i], sw[SB + O_CLW + j * 20 + 10 + i], s);
            float xph = fmaxf(s, 0.f);
            float xuh = dpu[j] * au + xl[j] * al;
            float s3 = 0.f;
#pragma unroll
            for (int i = 0; i < 10; i++) s3 = fmaf(xfv[i], sw[SB + O_DLW + j * 10 + i], s3);
            float xfh = fmaxf(attl * s3, 0.f);
            m[j] = xph + xuh + xfh;
        }
#pragma unroll
        for (int j = 0; j < 10; j++) {
            float g = sw[SB + O_GLB + j], cd = 0.f;
#pragma unroll
            for (int i = 0; i < 10; i++) {
                g  = fmaf(xl[i], sw[SB + O_GLW + j * 20 + i], g);
                cd = fmaf(xl[i], sw[SB + O_CDLW + j * 20 + i], cd);
            }
#pragma unroll
            for (int i = 0; i < 10; i++) {
                g  = fmaf(m[i], sw[SB + O_GLW + j * 20 + 10 + i], g);
                cd = fmaf(m[i], sw[SB + O_CDLW + j * 20 + 10 + i], cd);
            }
            g = sig1(g);
            cd = fmaxf(cd, 0.f);
            out[OUT_XHL + (n * 10 + j) * HW + pp] = fmaf(g, cd - xl[j], xl[j]);
        }
        out[OUT_ATTL + n * HW + pp] = attl;
    }
}

extern "C" void kernel_launch(void* const* d_in, const int* in_sizes, int n_in,
                              void* d_out, int out_size)
{
    k1_main<<<512, 128>>>(
        (const float*)d_in[0],   // h_fea
        (const float*)d_in[5],   // pdp_w1
        (const float*)d_in[15],  // decU_att_w
        (const float*)d_in[18]); // decL_att_w

    k2_post<<<1024, 128>>>(
        (const float*)d_in[1],  (const float*)d_in[2],
        (const float*)d_in[3],  (const float*)d_in[4],
        (const float*)d_in[5],  (const float*)d_in[6],
        (const float*)d_in[7],  (const float*)d_in[8],
        (const float*)d_in[9],  (const float*)d_in[10], (const float*)d_in[11],
        (const float*)d_in[12], (const float*)d_in[13], (const float*)d_in[14],
        (const float*)d_in[15], (const float*)d_in[16], (const float*)d_in[17],
        (const float*)d_in[18], (const float*)d_in[19], (const float*)d_in[20],
        (const float*)d_in[21], (const float*)d_in[22], (const float*)d_in[23],
        (const float*)d_in[24], (const float*)d_in[25], (const float*)d_in[26],
        (float*)d_out);
}

// round 9
// speedup vs baseline: 1.3521x; 1.1484x over previous
#include <cuda_runtime.h>

#define HW   16384      // 128*128
#define NCH  256
#define NB   8
#define PAIRS 65536     // 131072 pixels / 2
#define NPIX 131072

typedef unsigned long long u64;

// ---------------- packed f32x2 helpers (sm_103a) ----------------
__device__ __forceinline__ u64 fma2(u64 a, u64 b, u64 c) {
    u64 d; asm("fma.rn.f32x2 %0,%1,%2,%3;" : "=l"(d) : "l"(a), "l"(b), "l"(c)); return d;
}
__device__ __forceinline__ u64 add2(u64 a, u64 b) {
    u64 d; asm("add.rn.f32x2 %0,%1,%2;" : "=l"(d) : "l"(a), "l"(b)); return d;
}
__device__ __forceinline__ u64 pk2(float x, float y) {
    u64 r; asm("mov.b64 %0,{%1,%2};" : "=l"(r) : "f"(x), "f"(y)); return r;
}
__device__ __forceinline__ float sig1(float x) {
    return __fdividef(1.f, 1.f + __expf(-x));
}
__device__ __forceinline__ void pref_l2(const void* p) {
    asm volatile("prefetch.global.L2 [%0];" :: "l"(p));
}

// 22 partial dot products, f32 layout [o][pixel] (u64 = 2 adjacent px)
__device__ u64 g_scratch[22 * PAIRS];

// Output offsets (tuple flattened: xh_u_new, xh_l_new, att_u, att_l)
#define OUT_XHL  1310720
#define OUT_ATTU 2621440
#define OUT_ATTL 2752512

// =========================================================================
// Kernel 1: [px x 256] @ [256 x 22] streaming GEMM over h_fea.
//  - weights in smem as NON-duplicated pairs: sw[c*12 + o2] = (w_{2o2}, w_{2o2+1})
//  - pixel value duplicated in regs; fma2((x,x),(w0,w1),acc) -> 2 outputs/px
//  - 4 pixels/thread, channel-split 2 (thread handles 128 channels)
//  - partials combined in-block via smem staging (reuses weight region),
//    then coalesced transposed write of the single-copy scratch.
// =========================================================================
__global__ __launch_bounds__(128, 3) void k1_main(
    const float* __restrict__ h_fea,
    const float* __restrict__ pdp_w1,
    const float* __restrict__ dU_aw,
    const float* __restrict__ dL_aw)
{
    // union: weights (256*12 u64 = 24576 B) then staging (256 px * 11 u64 = 22528 B)
    __shared__ u64 smem_buf[3072];
    const int tid = threadIdx.x;

    // ---- weights: sw[c*12 + o2] = (w_{2o2}, w_{2o2+1}), o2 in [0,11) ----
    for (int idx = tid; idx < 256 * 12; idx += 128) {
        int c = idx / 12, o2 = idx - c * 12;
        float lo = 0.f, hi = 0.f;
        if (o2 < 10) {
            lo = pdp_w1[(2 * o2) * 276 + c];
            hi = pdp_w1[(2 * o2 + 1) * 276 + c];
        } else if (o2 == 10) {
            lo = dU_aw[c];
            hi = dL_aw[c];
        }
        smem_buf[idx] = pk2(lo, hi);
    }
    __syncthreads();

    const int g     = tid & 63;          // 4-px group within block
    const int chalf = tid >> 6;          // 0: channels [0,128), 1: [128,256)
    const int ch0   = chalf * 128;
    const int Pb    = blockIdx.x * 256;  // block pixel base (256 px/block)
    const int P0    = Pb + g * 4;
    const int n     = P0 >> 14;          // 16384/256=64 -> blocks never straddle n
    const int pp    = P0 & (HW - 1);
    const float* hb = h_fea + n * (NCH * HW) + ch0 * HW + pp;

    // acc[p][o2]: p in 0..3 pixels, o2 in 0..10 output-pairs
    u64 acc[44];
#pragma unroll
    for (int o = 0; o < 44; o++) acc[o] = 0ull;

    u64 bA[8], bB[8];   // 4 channels x 2 u64 (4 px)

#define LOAD_CHUNK(B, C0)                                                     \
    _Pragma("unroll")                                                         \
    for (int jj = 0; jj < 4; jj++) {                                          \
        B[2 * jj]     = *reinterpret_cast<const u64*>(hb + ((C0) + jj) * HW);     \
        B[2 * jj + 1] = *reinterpret_cast<const u64*>(hb + ((C0) + jj) * HW + 2); \
        pref_l2(hb + ((((C0) + jj + 32) & 127)) * HW);                        \
    }

#define COMP_CHUNK(B, C0)                                                     \
    _Pragma("unroll")                                                         \
    for (int jj = 0; jj < 4; jj++) {                                          \
        float2 xa = *reinterpret_cast<const float2*>(&B[2 * jj]);             \
        float2 xb = *reinterpret_cast<const float2*>(&B[2 * jj + 1]);         \
        u64 d0 = pk2(xa.x, xa.x), d1 = pk2(xa.y, xa.y);                       \
        u64 d2 = pk2(xb.x, xb.x), d3 = pk2(xb.y, xb.y);                       \
        const u64* wc = &smem_buf[(ch0 + (C0) + jj) * 12];                    \
        const ulonglong2* w2 = reinterpret_cast<const ulonglong2*>(wc);       \
        _Pragma("unroll")                                                     \
        for (int q = 0; q < 5; q++) {                                         \
            ulonglong2 wp = w2[q];                                            \
            acc[0 * 11 + 2 * q]     = fma2(d0, wp.x, acc[0 * 11 + 2 * q]);    \
            acc[1 * 11 + 2 * q]     = fma2(d1, wp.x, acc[1 * 11 + 2 * q]);    \
            acc[2 * 11 + 2 * q]     = fma2(d2, wp.x, acc[2 * 11 + 2 * q]);    \
            acc[3 * 11 + 2 * q]     = fma2(d3, wp.x, acc[3 * 11 + 2 * q]);    \
            acc[0 * 11 + 2 * q + 1] = fma2(d0, wp.y, acc[0 * 11 + 2 * q + 1]);\
            acc[1 * 11 + 2 * q + 1] = fma2(d1, wp.y, acc[1 * 11 + 2 * q + 1]);\
            acc[2 * 11 + 2 * q + 1] = fma2(d2, wp.y, acc[2 * 11 + 2 * q + 1]);\
            acc[3 * 11 + 2 * q + 1] = fma2(d3, wp.y, acc[3 * 11 + 2 * q + 1]);\
        }                                                                     \
        { u64 wA = wc[10];                                                    \
          acc[0 * 11 + 10] = fma2(d0, wA, acc[0 * 11 + 10]);                  \
          acc[1 * 11 + 10] = fma2(d1, wA, acc[1 * 11 + 10]);                  \
          acc[2 * 11 + 10] = fma2(d2, wA, acc[2 * 11 + 10]);                  \
          acc[3 * 11 + 10] = fma2(d3, wA, acc[3 * 11 + 10]); }                \
    }

    LOAD_CHUNK(bA, 0)
#pragma unroll 1
    for (int c0 = 0; c0 < 128; c0 += 8) {
        LOAD_CHUNK(bB, c0 + 4)
        COMP_CHUNK(bA, c0)
        const int nxt = (c0 + 8) & 127;   // last iter reloads chunk 0 (dead)
        LOAD_CHUNK(bA, nxt)
        COMP_CHUNK(bB, c0 + 4)
    }
#undef LOAD_CHUNK
#undef COMP_CHUNK

    // ---- combine the two channel halves inside the block ----
    __syncthreads();                      // weights dead; staging may reuse smem

    // staging layout: stag[p*11 + o2], p = pixel within block (0..255)
    if (chalf == 1) {
#pragma unroll
        for (int k = 0; k < 4; k++)
#pragma unroll
            for (int o2 = 0; o2 < 11; o2++)
                smem_buf[(g * 4 + k) * 11 + o2] = acc[k * 11 + o2];
    }
    __syncthreads();
    if (chalf == 0) {
#pragma unroll
        for (int k = 0; k < 4; k++)
#pragma unroll
            for (int o2 = 0; o2 < 11; o2++) {
                int s = (g * 4 + k) * 11 + o2;
                smem_buf[s] = add2(acc[k * 11 + o2], smem_buf[s]);
            }
    }
    __syncthreads();

    // ---- coalesced transposed write: scratch f32 layout [o][P] ----
    const float* stagf = reinterpret_cast<const float*>(smem_buf); // [p][22]
    float* gsf = reinterpret_cast<float*>(g_scratch);
    const int p0 = 2 * tid;               // two pixels per thread per output
#pragma unroll
    for (int o = 0; o < 22; o++) {
        float v0 = stagf[p0 * 22 + o];
        float v1 = stagf[(p0 + 1) * 22 + o];
        *reinterpret_cast<u64*>(gsf + o * NPIX + Pb + p0) = pk2(v0, v1);
    }
}

// =========================================================================
// Kernel 2: tails + graph logic — SCALAR, 1 pixel/thread. (R4-identical)
// =========================================================================
#define SB 440
#define O_W2    0
#define O_ATTW  200
#define O_ATTB  220
#define O_CUAW  222
#define O_CUAB  262
#define O_CUW   266
#define O_CLAW  466
#define O_CLAB  486
#define O_CLW   488
#define O_DUB   688
#define O_DUW   689
#define O_DLB   789
#define O_DLW   790
#define O_GUW   890
#define O_GUB   1090
#define O_CDUW  1100
#define O_GLW   1300
#define O_GLB   1500
#define O_CDLW  1510
#define SM2_F32 (SB + 1710)

__global__ __launch_bounds__(128, 4) void k2_post(
    const float* __restrict__ xh_u, const float* __restrict__ xh_l,
    const float* __restrict__ xf, const float* __restrict__ xp,
    const float* __restrict__ pdp_w1, const float* __restrict__ pdp_w2,
    const float* __restrict__ att_w, const float* __restrict__ att_b,
    const float* __restrict__ cU_aw, const float* __restrict__ cU_ab, const float* __restrict__ cU_w,
    const float* __restrict__ cL_aw, const float* __restrict__ cL_ab, const float* __restrict__ cL_w,
    const float* __restrict__ dU_aw, const float* __restrict__ dU_ab, const float* __restrict__ dU_w,
    const float* __restrict__ dL_aw, const float* __restrict__ dL_ab, const float* __restrict__ dL_w,
    const float* __restrict__ gU_w, const float* __restrict__ gU_b, const float* __restrict__ cdU_w,
    const float* __restrict__ gL_w, const float* __restrict__ gL_b, const float* __restrict__ cdL_w,
    float* __restrict__ out)
{
    __shared__ float sw[SM2_F32];           // 8.6 KB
    const int tid = threadIdx.x;

    for (int idx = tid; idx < 400; idx += 128) {
        int o = idx / 20, i = idx - o * 20;
        sw[idx] = pdp_w1[o * 276 + 256 + i];      // cat [h_fea, xh_u, xh_l]
    }
    if (tid < 20) {
        sw[400 + tid] = dU_aw[256 + tid];         // [h_fea, xf, xh_u]
        sw[420 + tid] = dL_aw[256 + tid];         // [h_fea, xf, xh_l]
    }
#define CPY(src, n_, off) for (int j = tid; j < (n_); j += 128) sw[SB + (off) + j] = (src)[j];
    CPY(pdp_w2, 200, O_W2)
    CPY(att_w, 20, O_ATTW)
    CPY(att_b, 2, O_ATTB)
    CPY(cU_aw, 40, O_CUAW)
    CPY(cU_ab, 4, O_CUAB)
    CPY(cU_w, 200, O_CUW)
    CPY(cL_aw, 20, O_CLAW)
    CPY(cL_ab, 2, O_CLAB)
    CPY(cL_w, 200, O_CLW)
    CPY(dU_ab, 1, O_DUB)
    CPY(dU_w, 100, O_DUW)
    CPY(dL_ab, 1, O_DLB)
    CPY(dL_w, 100, O_DLW)
    CPY(gU_w, 200, O_GUW)
    CPY(gU_b, 10, O_GUB)
    CPY(cdU_w, 200, O_CDUW)
    CPY(gL_w, 200, O_GLW)
    CPY(gL_b, 10, O_GLB)
    CPY(cdL_w, 200, O_CDLW)
#undef CPY
    __syncthreads();

    const int P  = blockIdx.x * 128 + tid;  // one pixel per thread
    const int n  = P >> 14;
    const int pp = P & (HW - 1);

    const float* gsf = reinterpret_cast<const float*>(g_scratch);

    float acc[22];
#pragma unroll
    for (int o = 0; o < 22; o++) acc[o] = gsf[o * NPIX + P];

    const int base10 = n * 10 * HW + pp;
    float xu[10], xl[10], xfv[10];
#pragma unroll
    for (int i = 0; i < 10; i++) {
        xu[i]  = xh_u[base10 + i * HW];
        xl[i]  = xh_l[base10 + i * HW];
        xfv[i] = xf[base10 + i * HW];
    }

    // tails of the 276-channel dot products
#pragma unroll
    for (int o = 0; o < 20; o++) {
        float a = acc[o];
#pragma unroll
        for (int i = 0; i < 10; i++) {
            a = fmaf(xu[i], sw[o * 20 + i], a);
            a = fmaf(xl[i], sw[o * 20 + 10 + i], a);
        }
        acc[o] = a;
    }
    {
        float a = acc[20];
#pragma unroll
        for (int i = 0; i < 10; i++) {
            a = fmaf(xfv[i], sw[400 + i], a);
            a = fmaf(xu[i],  sw[410 + i], a);
        }
        acc[20] = a;
        float b = acc[21];
#pragma unroll
        for (int i = 0; i < 10; i++) {
            b = fmaf(xfv[i], sw[420 + i], b);
            b = fmaf(xl[i],  sw[430 + i], b);
        }
        acc[21] = b;
    }

    const float attu = sig1(acc[20] + sw[SB + O_DUB]);
    const float attl = sig1(acc[21] + sw[SB + O_DLB]);

#pragma unroll
    for (int o = 0; o < 20; o++) acc[o] = fmaxf(acc[o], 0.f);

    // dp grouped 10x10
    float dpu[10], dpl[10];
#pragma unroll
    for (int j = 0; j < 10; j++) {
        float s = 0.f, s2 = 0.f;
#pragma unroll
        for (int i = 0; i < 10; i++) {
            s  = fmaf(acc[i],      sw[SB + O_W2 + j * 10 + i], s);
            s2 = fmaf(acc[10 + i], sw[SB + O_W2 + 100 + j * 10 + i], s2);
        }
        dpu[j] = fmaxf(s, 0.f);
        dpl[j] = fmaxf(s2, 0.f);
    }

    // grouped gate attention
    float au = sw[SB + O_ATTB + 0], al = sw[SB + O_ATTB + 1];
#pragma unroll
    for (int i = 0; i < 10; i++) {
        au = fmaf(xu[i], sw[SB + O_ATTW + i], au);
        al = fmaf(xl[i], sw[SB + O_ATTW + 10 + i], al);
    }
    au = sig1(au);
    al = sig1(al);

    float m[10];

    // =================== U branch ===================
    {
        float msg0 = 0.f, msg1 = 0.f, msg2 = 0.f, msg3 = 0.f, msg4 = 0.f,
              msg5 = 0.f, msg6 = 0.f, msg7 = 0.f, msg8 = 0.f, msg9 = 0.f;
#pragma unroll
        for (int p = 0; p < 4; p++) {
            float ca = sw[SB + O_CUAB + p];
            float pv[10];
#pragma unroll
            for (int i = 0; i < 10; i++) {
                pv[i] = xp[((p * NB + n) * 10 + i) * HW + pp];
                ca = fmaf(pv[i], sw[SB + O_CUAW + p * 10 + i], ca);
            }
            ca = sig1(ca);
            msg0 = fmaf(pv[0], ca, msg0); msg1 = fmaf(pv[1], ca, msg1);
            msg2 = fmaf(pv[2], ca, msg2); msg3 = fmaf(pv[3], ca, msg3);
            msg4 = fmaf(pv[4], ca, msg4); msg5 = fmaf(pv[5], ca, msg5);
            msg6 = fmaf(pv[6], ca, msg6); msg7 = fmaf(pv[7], ca, msg7);
            msg8 = fmaf(pv[8], ca, msg8); msg9 = fmaf(pv[9], ca, msg9);
        }
        float msg[10] = {msg0, msg1, msg2, msg3, msg4, msg5, msg6, msg7, msg8, msg9};
#pragma unroll
        for (int j = 0; j < 10; j++) {
            float s = 0.f;
#pragma unroll
            for (int i = 0; i < 10; i++) s = fmaf(xu[i],  sw[SB + O_CUW + j * 20 + i], s);
#pragma unroll
            for (int i = 0; i < 10; i++) s = fmaf(msg[i], sw[SB + O_CUW + j * 20 + 10 + i], s);
            float xph = fmaxf(s, 0.f);
            float xlh = dpl[j] * al + xu[j] * au;
            float s3 = 0.f;
#pragma unroll
            for (int i = 0; i < 10; i++) s3 = fmaf(xfv[i], sw[SB + O_DUW + j * 10 + i], s3);
            float xfh = fmaxf(attu * s3, 0.f);
            m[j] = xph + xlh + xfh;
        }
#pragma unroll
        for (int j = 0; j < 10; j++) {
            float g = sw[SB + O_GUB + j], cd = 0.f;
#pragma unroll
            for (int i = 0; i < 10; i++) {
                g  = fmaf(xu[i], sw[SB + O_GUW + j * 20 + i], g);
                cd = fmaf(xu[i], sw[SB + O_CDUW + j * 20 + i], cd);
            }
#pragma unroll
            for (int i = 0; i < 10; i++) {
                g  = fmaf(m[i], sw[SB + O_GUW + j * 20 + 10 + i], g);
                cd = fmaf(m[i], sw[SB + O_CDUW + j * 20 + 10 + i], cd);
            }
            g = sig1(g);
            cd = fmaxf(cd, 0.f);
            out[(n * 10 + j) * HW + pp] = fmaf(g, cd - xu[j], xu[j]);
        }
        out[OUT_ATTU + n * HW + pp] = attu;
    }

    // =================== L branch ===================
    {
        float msg0 = 0.f, msg1 = 0.f, msg2 = 0.f, msg3 = 0.f, msg4 = 0.f,
              msg5 = 0.f, msg6 = 0.f, msg7 = 0.f, msg8 = 0.f, msg9 = 0.f;
#pragma unroll
        for (int p = 0; p < 2; p++) {
            float ca = sw[SB + O_CLAB + p];
            float pv[10];
#pragma unroll
            for (int i = 0; i < 10; i++) {
                pv[i] = xp[(((p + 4) * NB + n) * 10 + i) * HW + pp];
                ca = fmaf(pv[i], sw[SB + O_CLAW + p * 10 + i], ca);
            }
            ca = sig1(ca);
            msg0 = fmaf(pv[0], ca, msg0); msg1 = fmaf(pv[1], ca, msg1);
            msg2 = fmaf(pv[2], ca, msg2); msg3 = fmaf(pv[3], ca, msg3);
            msg4 = fmaf(pv[4], ca, msg4); msg5 = fmaf(pv[5], ca, msg5);
            msg6 = fmaf(pv[6], ca, msg6); msg7 = fmaf(pv[7], ca, msg7);
            msg8 = fmaf(pv[8], ca, msg8); msg9 = fmaf(pv[9], ca, msg9);
        }
        float msg[10] = {msg0, msg1, msg2, msg3, msg4, msg5, msg6, msg7, msg8, msg9};
#pragma unroll
        for (int j = 0; j < 10; j++) {
            float s = 0.f;
#pragma unroll
            for (int i = 0; i < 10; i++) s = fmaf(xl[i],  sw[SB + O_CLW + j * 20 + i], s);
#pragma unroll
            for (int i = 0; i < 10; i++) s = fmaf(msg[i], sw[SB + O_CLW + j * 20 + 10 + i], s);
            float xph = fmaxf(s, 0.f);
            float xuh = dpu[j] * au + xl[j] * al;
            float s3 = 0.f;
#pragma unroll
            for (int i = 0; i < 10; i++) s3 = fmaf(xfv[i], sw[SB + O_DLW + j * 10 + i], s3);
            float xfh = fmaxf(attl * s3, 0.f);
            m[j] = xph + xuh + xfh;
        }
#pragma unroll
        for (int j = 0; j < 10; j++) {
            float g = sw[SB + O_GLB + j], cd = 0.f;
#pragma unroll
            for (int i = 0; i < 10; i++) {
                g  = fmaf(xl[i], sw[SB + O_GLW + j * 20 + i], g);
                cd = fmaf(xl[i], sw[SB + O_CDLW + j * 20 + i], cd);
            }
#pragma unroll
            for (int i = 0; i < 10; i++) {
                g  = fmaf(m[i], sw[SB + O_GLW + j * 20 + 10 + i], g);
                cd = fmaf(m[i], sw[SB + O_CDLW + j * 20 + 10 + i], cd);
            }
            g = sig1(g);
            cd = fmaxf(cd, 0.f);
            out[OUT_XHL + (n * 10 + j) * HW + pp] = fmaf(g, cd - xl[j], xl[j]);
        }
        out[OUT_ATTL + n * HW + pp] = attl;
    }
}

extern "C" void kernel_launch(void* const* d_in, const int* in_sizes, int n_in,
                              void* d_out, int out_size)
{
    k1_main<<<512, 128>>>(
        (const float*)d_in[0],   // h_fea
        (const float*)d_in[5],   // pdp_w1
        (const float*)d_in[15],  // decU_att_w
        (const float*)d_in[18]); // decL_att_w

    k2_post<<<1024, 128>>>(
        (const float*)d_in[1],  (const float*)d_in[2],
        (const float*)d_in[3],  (const float*)d_in[4],
        (const float*)d_in[5],  (const float*)d_in[6],
        (const float*)d_in[7],  (const float*)d_in[8],
        (const float*)d_in[9],  (const float*)d_in[10], (const float*)d_in[11],
        (const float*)d_in[12], (const float*)d_in[13], (const float*)d_in[14],
        (const float*)d_in[15], (const float*)d_in[16], (const float*)d_in[17],
        (const float*)d_in[18], (const float*)d_in[19], (const float*)d_in[20],
        (const float*)d_in[21], (const float*)d_in[22], (const float*)d_in[23],
        (const float*)d_in[24], (const float*)d_in[25], (const float*)d_in[26],
        (float*)d_out);
}